// round 4
// baseline (speedup 1.0000x reference)
#include <cuda_runtime.h>
#include <math.h>
#include <stdint.h>

#define BATCH 32
#define SEQ   2048
#define HID   512

typedef unsigned long long ull;

// Scratch (static device globals: allocation-free)
__device__ float g_xproj[SEQ * BATCH * HID];   // [s][b][h] layout
__device__ float g_hfin[BATCH * HID];          // final hidden state

// ---------------------------------------------------------------------------
// packed f32x2 helpers (FFMA2 only reachable via PTX)
// ---------------------------------------------------------------------------
__device__ __forceinline__ void ffma2(ull& acc, ull a, ull b) {
    asm("fma.rn.f32x2 %0, %1, %2, %0;" : "+l"(acc) : "l"(a), "l"(b));
}
__device__ __forceinline__ ull dup2(float v) {
    ull r; asm("mov.b64 %0, {%1, %1};" : "=l"(r) : "f"(v)); return r;
}
__device__ __forceinline__ float2 unpk(ull v) {
    float2 r; asm("mov.b64 {%0, %1}, %2;" : "=f"(r.x), "=f"(r.y) : "l"(v)); return r;
}
// fast tanh: 1 - 2/(e^{2x}+1); saturates to +-1, no NaN path.
__device__ __forceinline__ float ftanh(float x) {
    float e = __expf(x + x);
    return 1.f - __fdividef(2.f, e + 1.f);
}

// ---------------------------------------------------------------------------
// Kernel 1: xproj = x @ W_xh^T + (b_xh + b_hh + b_h), written as [s][b][h]
// (unchanged from R3: 128x128 tile, FFMA2, reg double-buffer)
// ---------------------------------------------------------------------------
__global__ __launch_bounds__(256, 2) void xproj_gemm(
    const float* __restrict__ X,
    const float* __restrict__ Wxh,
    const float* __restrict__ bxh,
    const float* __restrict__ bhh,
    const float* __restrict__ bh)
{
    __shared__ float As[8][128];
    __shared__ float Bs[8][128];
    const int K = HID;
    const int n0 = blockIdx.x * 128;
    const int m0 = blockIdx.y * 128;
    const int tid = threadIdx.x;

    const int lr = tid >> 1;
    const int lc = (tid & 1) << 2;
    const int ca = (tid & 15) << 2;
    const int ra = (tid >> 4) << 2;

    ull acc[8][4];
#pragma unroll
    for (int i = 0; i < 8; i++)
#pragma unroll
        for (int j = 0; j < 4; j++) acc[i][j] = 0ull;

    const float* Aptr = X   + (size_t)(m0 + lr) * K + lc;
    const float* Bptr = Wxh + (size_t)(n0 + lr) * K + lc;

    float4 a4 = *(const float4*)(Aptr);
    float4 b4 = *(const float4*)(Bptr);

    for (int k0 = 0; k0 < K; k0 += 8) {
        As[lc + 0][lr] = a4.x; As[lc + 1][lr] = a4.y;
        As[lc + 2][lr] = a4.z; As[lc + 3][lr] = a4.w;
        Bs[lc + 0][lr] = b4.x; Bs[lc + 1][lr] = b4.y;
        Bs[lc + 2][lr] = b4.z; Bs[lc + 3][lr] = b4.w;
        __syncthreads();
        if (k0 + 8 < K) {
            a4 = *(const float4*)(Aptr + k0 + 8);
            b4 = *(const float4*)(Bptr + k0 + 8);
        }
#pragma unroll
        for (int k = 0; k < 8; k++) {
            float am[8];
            *(float4*)&am[0] = *(const float4*)&As[k][ra];
            *(float4*)&am[4] = *(const float4*)&As[k][ra + 64];
            ulonglong2 b01 = *(const ulonglong2*)&Bs[k][ca];
            ulonglong2 b23 = *(const ulonglong2*)&Bs[k][ca + 64];
#pragma unroll
            for (int i = 0; i < 8; i++) {
                ull ad = dup2(am[i]);
                ffma2(acc[i][0], ad, b01.x);
                ffma2(acc[i][1], ad, b01.y);
                ffma2(acc[i][2], ad, b23.x);
                ffma2(acc[i][3], ad, b23.y);
            }
        }
        __syncthreads();
    }

    float biasv[8];
#pragma unroll
    for (int j = 0; j < 8; j++) {
        int n = n0 + ((j < 4) ? (ca + j) : (64 + ca + j - 4));
        biasv[j] = bxh[n] + bhh[n] + bh[n];
    }

#pragma unroll
    for (int i = 0; i < 8; i++) {
        int m = m0 + ((i < 4) ? (ra + i) : (64 + ra + i - 4));
        int b = m >> 11;
        int s = m & (SEQ - 1);
        float* outr = &g_xproj[((size_t)s * BATCH + b) * HID + n0];
        float2 p0 = unpk(acc[i][0]);
        float2 p1 = unpk(acc[i][1]);
        float2 p2 = unpk(acc[i][2]);
        float2 p3 = unpk(acc[i][3]);
        float4 v0, v1;
        v0.x = p0.x + biasv[0]; v0.y = p0.y + biasv[1];
        v0.z = p1.x + biasv[2]; v0.w = p1.y + biasv[3];
        v1.x = p2.x + biasv[4]; v1.y = p2.y + biasv[5];
        v1.z = p3.x + biasv[6]; v1.w = p3.y + biasv[7];
        *(float4*)&outr[ca]      = v0;
        *(float4*)&outr[64 + ca] = v1;
    }
}

// ---------------------------------------------------------------------------
// Kernel 2: persistent recurrent scan. 16 clusters x 8 CTAs; cluster = 2
// batches, CTA rank = 64 hidden rows. Warp w owns rows i0+w*4..+4 (both
// batches); lane l owns K-subset {c*128 + l*4 + 0..3}. Weights in registers
// (f32x2 pairs). Reduce via xor-shfl all-reduce. Exchange: remote
// st.shared::cluster.v4 + per-CTA mbarrier (8 remote release-arrives).
// ---------------------------------------------------------------------------
__global__ __launch_bounds__(512, 1) __cluster_dims__(8, 1, 1)
void scan_kernel(const float* __restrict__ Whh)
{
    __shared__ float hs[2][2][HID];            // [buf][batch][k]  8KB
    __shared__ __align__(8) ull mbar;

    const int tid = threadIdx.x;
    const int w = tid >> 5, l = tid & 31;

    unsigned rank;
    asm("mov.u32 %0, %%cluster_ctarank;" : "=r"(rank));
    const int b0 = (int)(blockIdx.x >> 3) * 2;
    const int i0 = (int)rank * 64;

    // Weights: rows i0+w*4+r, k = c*128 + l*4 + {0..3}, as f32x2 pairs.
    ull wp[4][4][2];
#pragma unroll
    for (int r = 0; r < 4; r++)
#pragma unroll
        for (int c = 0; c < 4; c++) {
            ulonglong2 u = *(const ulonglong2*)
                (&Whh[(size_t)(i0 + w * 4 + r) * HID + c * 128 + l * 4]);
            wp[r][c][0] = u.x; wp[r][c][1] = u.y;
        }

    const uint32_t mb = (uint32_t)__cvta_generic_to_shared(&mbar);
    if (tid == 0)
        asm volatile("mbarrier.init.shared.b64 [%0], %1;" :: "r"(mb), "r"(8u) : "memory");
    for (int i = tid; i < 2 * HID; i += 512) ((float*)hs[0])[i] = 0.f;  // h(0)=0
    __syncthreads();
    asm volatile("barrier.cluster.arrive.aligned;" ::: "memory");
    asm volatile("barrier.cluster.wait.aligned;" ::: "memory");

    // xproj prefetch ring (lanes 0..7 per warp own the warp's 8 outputs)
    const int j  = l & 7;
    const int rj = j & 3, bj = j >> 2;
    const float* xpp = &g_xproj[(size_t)(b0 + bj) * HID + i0 + w * 4 + rj];
    float xpA = 0.f, xpB = 0.f;
    if (l < 8) {
        xpA = __ldcg(xpp);
        xpB = __ldcg(xpp + BATCH * HID);
        xpp += 2 * BATCH * HID;
    }

    for (int s = 0; s < SEQ; s++) {
        const int cur = s & 1, nxt = cur ^ 1;

        // prefetch xp[s+2] before the spin (hides DRAM latency)
        float xpC = 0.f;
        if (l < 8 && s + 2 < SEQ) { xpC = __ldcg(xpp); xpp += BATCH * HID; }

        // wait for h(s) delivery (completion #s); s==0 is local zeros
        if (s > 0) {
            uint32_t P = (uint32_t)((s - 1) & 1);
            asm volatile(
                "{\n\t.reg .pred p;\n\t"
                "W%=:\n\t"
                "mbarrier.try_wait.parity.acquire.cluster.shared::cta.b64 p, [%0], %1;\n\t"
                "@!p bra W%=;\n\t}"
                :: "r"(mb), "r"(P) : "memory");
        }

        // matvec: v[b*4+r] = sum_K W[i0+w*4+r][k] * h[b][k] (my K-subset)
        float v[8];
#pragma unroll
        for (int b = 0; b < 2; b++) {
            ulonglong2 hc[4];
#pragma unroll
            for (int c = 0; c < 4; c++)
                hc[c] = *(const ulonglong2*)&hs[cur][b][c * 128 + l * 4];
            ull acc[4] = {0ull, 0ull, 0ull, 0ull};
#pragma unroll
            for (int c = 0; c < 4; c++)
#pragma unroll
                for (int r = 0; r < 4; r++) {
                    ffma2(acc[r], wp[r][c][0], hc[c].x);
                    ffma2(acc[r], wp[r][c][1], hc[c].y);
                }
#pragma unroll
            for (int r = 0; r < 4; r++) {
                float2 u = unpk(acc[r]);
                v[b * 4 + r] = u.x + u.y;
            }
        }

        // xor-shfl all-reduce of the 8 dots across the warp
#pragma unroll
        for (int o = 16; o >= 1; o >>= 1)
#pragma unroll
            for (int i = 0; i < 8; i++)
                v[i] += __shfl_xor_sync(0xffffffffu, v[i], o);

        // lane j (<8) finishes its output
        float ft = 0.f;
        if (l < 8) {
            float myv = v[0];
            if (j == 1) myv = v[1];
            if (j == 2) myv = v[2];
            if (j == 3) myv = v[3];
            if (j == 4) myv = v[4];
            if (j == 5) myv = v[5];
            if (j == 6) myv = v[6];
            if (j == 7) myv = v[7];
            ft = ftanh(myv + xpA);
        }
        // gather rows r=0..3 into lanes 0 (batch0) and 4 (batch1)
        float t1 = __shfl_sync(0xffffffffu, ft, (l & ~3) + 1);
        float t2 = __shfl_sync(0xffffffffu, ft, (l & ~3) + 2);
        float t3 = __shfl_sync(0xffffffffu, ft, (l & ~3) + 3);
        if (l < 8 && (l & 3) == 0) {
            int b = l >> 2;
            uint32_t loff = (uint32_t)__cvta_generic_to_shared(
                &hs[nxt][b][i0 + w * 4]);
#pragma unroll
            for (int p = 0; p < 8; p++) {
                uint32_t ra;
                asm("mapa.shared::cluster.u32 %0, %1, %2;" : "=r"(ra) : "r"(loff), "r"(p));
                asm volatile("st.shared::cluster.v4.f32 [%0], {%1, %2, %3, %4};"
                             :: "r"(ra), "f"(ft), "f"(t1), "f"(t2), "f"(t3) : "memory");
            }
        }
        __syncthreads();
        if (tid < 8) {
            asm volatile("fence.acq_rel.cluster;" ::: "memory");
            uint32_t ra;
            asm("mapa.shared::cluster.u32 %0, %1, %2;" : "=r"(ra) : "r"(mb), "r"(tid));
            asm volatile("mbarrier.arrive.release.cluster.shared::cluster.b64 _, [%0];"
                         :: "r"(ra) : "memory");
        }
        xpA = xpB; xpB = xpC;
    }

    // wait for completion #SEQ (h(SEQ) delivered into hs[0])
    {
        uint32_t P = (uint32_t)((SEQ - 1) & 1);
        asm volatile(
            "{\n\t.reg .pred p;\n\t"
            "W%=:\n\t"
            "mbarrier.try_wait.parity.acquire.cluster.shared::cta.b64 p, [%0], %1;\n\t"
            "@!p bra W%=;\n\t}"
            :: "r"(mb), "r"(P) : "memory");
    }
    if (tid < 128) {
        int b = tid >> 6, row = tid & 63;
        g_hfin[(b0 + b) * HID + i0 + row] = hs[0][b][i0 + row];
    }
}

// ---------------------------------------------------------------------------
// Kernel 3: out = h_final @ W_fc^T + b_fc.
// ---------------------------------------------------------------------------
__global__ __launch_bounds__(256) void fc_kernel(
    const float* __restrict__ Wfc, const float* __restrict__ bfc,
    float* __restrict__ out)
{
    __shared__ float hsm[HID];
    const int b = blockIdx.x;
    const int o0 = blockIdx.y * 32;
    const int tid = threadIdx.x;
    for (int i = tid; i < HID; i += 256) hsm[i] = g_hfin[b * HID + i];
    __syncthreads();
    const int w = tid >> 5, l = tid & 31;
#pragma unroll
    for (int oi = 0; oi < 4; oi++) {
        int o = o0 + w * 4 + oi;
        const float* wr = Wfc + (size_t)o * HID;
        float sum = 0.f;
#pragma unroll
        for (int j2 = 0; j2 < HID / 32; j2++)
            sum = fmaf(hsm[j2 * 32 + l], wr[j2 * 32 + l], sum);
#pragma unroll
        for (int off = 16; off > 0; off >>= 1)
            sum += __shfl_down_sync(0xffffffffu, sum, off);
        if (l == 0) out[b * HID + o] = sum + bfc[o];
    }
}

// ---------------------------------------------------------------------------
extern "C" void kernel_launch(void* const* d_in, const int* in_sizes, int n_in,
                              void* d_out, int out_size)
{
    const float* x   = (const float*)d_in[0];
    const float* Wxh = (const float*)d_in[1];
    const float* bxh = (const float*)d_in[2];
    const float* Whh = (const float*)d_in[3];
    const float* bhh = (const float*)d_in[4];
    const float* bh  = (const float*)d_in[5];
    const float* Wfc = (const float*)d_in[6];
    const float* bfc = (const float*)d_in[7];
    float* out = (float*)d_out;

    xproj_gemm<<<dim3(HID / 128, (BATCH * SEQ) / 128), 256>>>(x, Wxh, bxh, bhh, bh);
    scan_kernel<<<128, 512>>>(Whh);
    fc_kernel<<<dim3(BATCH, 16), 256>>>(Wfc, bfc, out);
}

// round 6
// speedup vs baseline: 1.5687x; 1.5687x over previous
#include <cuda_runtime.h>
#include <math.h>
#include <stdint.h>

#define BATCH 32
#define SEQ   2048
#define HID   512

typedef unsigned long long ull;

// Scratch (static device globals: allocation-free)
__device__ float g_xproj[SEQ * BATCH * HID];   // [s][b][h] layout
__device__ float g_hfin[BATCH * HID];          // final hidden state

// ---------------------------------------------------------------------------
// packed f32x2 helpers (FFMA2 only reachable via PTX)
// ---------------------------------------------------------------------------
__device__ __forceinline__ void ffma2(ull& acc, ull a, ull b) {
    asm("fma.rn.f32x2 %0, %1, %2, %0;" : "+l"(acc) : "l"(a), "l"(b));
}
__device__ __forceinline__ ull dup2(float v) {
    ull r; asm("mov.b64 %0, {%1, %1};" : "=l"(r) : "f"(v)); return r;
}
__device__ __forceinline__ float2 unpk(ull v) {
    float2 r; asm("mov.b64 {%0, %1}, %2;" : "=f"(r.x), "=f"(r.y) : "l"(v)); return r;
}
// fast tanh: 1 - 2/(e^{2x}+1); saturates to +-1, no NaN path.
__device__ __forceinline__ float ftanh(float x) {
    float e = __expf(x + x);
    return 1.f - __fdividef(2.f, e + 1.f);
}

// ---------------------------------------------------------------------------
// Kernel 1: xproj = x @ W_xh^T + (b_xh + b_hh + b_h), written as [s][b][h]
// (unchanged: 128x128 tile, FFMA2, reg double-buffer)
// ---------------------------------------------------------------------------
__global__ __launch_bounds__(256, 2) void xproj_gemm(
    const float* __restrict__ X,
    const float* __restrict__ Wxh,
    const float* __restrict__ bxh,
    const float* __restrict__ bhh,
    const float* __restrict__ bh)
{
    __shared__ float As[8][128];
    __shared__ float Bs[8][128];
    const int K = HID;
    const int n0 = blockIdx.x * 128;
    const int m0 = blockIdx.y * 128;
    const int tid = threadIdx.x;

    const int lr = tid >> 1;
    const int lc = (tid & 1) << 2;
    const int ca = (tid & 15) << 2;
    const int ra = (tid >> 4) << 2;

    ull acc[8][4];
#pragma unroll
    for (int i = 0; i < 8; i++)
#pragma unroll
        for (int j = 0; j < 4; j++) acc[i][j] = 0ull;

    const float* Aptr = X   + (size_t)(m0 + lr) * K + lc;
    const float* Bptr = Wxh + (size_t)(n0 + lr) * K + lc;

    float4 a4 = *(const float4*)(Aptr);
    float4 b4 = *(const float4*)(Bptr);

    for (int k0 = 0; k0 < K; k0 += 8) {
        As[lc + 0][lr] = a4.x; As[lc + 1][lr] = a4.y;
        As[lc + 2][lr] = a4.z; As[lc + 3][lr] = a4.w;
        Bs[lc + 0][lr] = b4.x; Bs[lc + 1][lr] = b4.y;
        Bs[lc + 2][lr] = b4.z; Bs[lc + 3][lr] = b4.w;
        __syncthreads();
        if (k0 + 8 < K) {
            a4 = *(const float4*)(Aptr + k0 + 8);
            b4 = *(const float4*)(Bptr + k0 + 8);
        }
#pragma unroll
        for (int k = 0; k < 8; k++) {
            float am[8];
            *(float4*)&am[0] = *(const float4*)&As[k][ra];
            *(float4*)&am[4] = *(const float4*)&As[k][ra + 64];
            ulonglong2 b01 = *(const ulonglong2*)&Bs[k][ca];
            ulonglong2 b23 = *(const ulonglong2*)&Bs[k][ca + 64];
#pragma unroll
            for (int i = 0; i < 8; i++) {
                ull ad = dup2(am[i]);
                ffma2(acc[i][0], ad, b01.x);
                ffma2(acc[i][1], ad, b01.y);
                ffma2(acc[i][2], ad, b23.x);
                ffma2(acc[i][3], ad, b23.y);
            }
        }
        __syncthreads();
    }

    float biasv[8];
#pragma unroll
    for (int j = 0; j < 8; j++) {
        int n = n0 + ((j < 4) ? (ca + j) : (64 + ca + j - 4));
        biasv[j] = bxh[n] + bhh[n] + bh[n];
    }

#pragma unroll
    for (int i = 0; i < 8; i++) {
        int m = m0 + ((i < 4) ? (ra + i) : (64 + ra + i - 4));
        int b = m >> 11;
        int s = m & (SEQ - 1);
        float* outr = &g_xproj[((size_t)s * BATCH + b) * HID + n0];
        float2 p0 = unpk(acc[i][0]);
        float2 p1 = unpk(acc[i][1]);
        float2 p2 = unpk(acc[i][2]);
        float2 p3 = unpk(acc[i][3]);
        float4 v0, v1;
        v0.x = p0.x + biasv[0]; v0.y = p0.y + biasv[1];
        v0.z = p1.x + biasv[2]; v0.w = p1.y + biasv[3];
        v1.x = p2.x + biasv[4]; v1.y = p2.y + biasv[5];
        v1.z = p3.x + biasv[6]; v1.w = p3.y + biasv[7];
        *(float4*)&outr[ca]      = v0;
        *(float4*)&outr[64 + ca] = v1;
    }
}

// ---------------------------------------------------------------------------
// Kernel 2: persistent recurrent scan. 16 clusters x 8 CTAs; cluster = 2
// batches, CTA rank = 64 hidden rows. Warp w owns rows i0+w*4..+4 for both
// batches; lane l owns K-subset {c*128 + l*4 + 0..3}. Weights in registers
// (f32x2 pairs). Warp-local fold+butterfly shfl reduce (no smem partials, no
// __syncthreads in loop). Exchange: lanes 0..7 each store the 4-row v4 vector
// to 2 peer CTAs (lane spreads the 8-peer fanout). Sync: split cluster barrier.
// ---------------------------------------------------------------------------
__global__ __launch_bounds__(512, 1) __cluster_dims__(8, 1, 1)
void scan_kernel(const float* __restrict__ Whh)
{
    __shared__ float hs[2][2][HID];            // [buf][batch][k]  8KB

    const int tid = threadIdx.x;
    const int w = tid >> 5, l = tid & 31;

    unsigned rank;
    asm("mov.u32 %0, %%cluster_ctarank;" : "=r"(rank));
    const int b0 = (int)(blockIdx.x >> 3) * 2;
    const int i0 = (int)rank * 64;

    // Weights: rows i0+w*4+r, k = c*128 + l*4 + {0..3}, as f32x2 pairs.
    ull wp[4][4][2];
#pragma unroll
    for (int r = 0; r < 4; r++)
#pragma unroll
        for (int c = 0; c < 4; c++) {
            ulonglong2 u = *(const ulonglong2*)
                (&Whh[(size_t)(i0 + w * 4 + r) * HID + c * 128 + l * 4]);
            wp[r][c][0] = u.x; wp[r][c][1] = u.y;
        }

    // Remote-store peer bases (mapa once). Lane l<8 covers peers 2(l&3), +1.
    uint32_t hbase = (uint32_t)__cvta_generic_to_shared(&hs[0][0][0]);
    uint32_t ra0 = 0, ra1 = 0;
    if (l < 8) {
        int p0 = (l & 3) * 2;
        asm("mapa.shared::cluster.u32 %0, %1, %2;" : "=r"(ra0) : "r"(hbase), "r"(p0));
        asm("mapa.shared::cluster.u32 %0, %1, %2;" : "=r"(ra1) : "r"(hbase), "r"(p0 + 1));
    }

    // rep lanes (l%4==0) own (batch brep, row w*4+rrep) after the fold-reduce
    const int brep = (l >> 2) & 1;
    const int rrep = ((l >> 3) & 1) * 2 + ((l >> 4) & 1);
    const bool isrep = ((l & 3) == 0);

    // h(0) = 0 (each CTA zeroes its own buffer 0)
    for (int i = tid; i < 2 * HID; i += 512) ((float*)hs[0])[i] = 0.f;
    __syncthreads();
    asm volatile("barrier.cluster.arrive.aligned;" ::: "memory");   // arrive #0

    // xproj prefetch ring, 2 deep, on rep lanes
    const float* xpp = &g_xproj[(size_t)(b0 + brep) * HID + i0 + w * 4 + rrep];
    float xpA = 0.f, xpB = 0.f;
    if (isrep) {
        xpA = __ldcg(xpp);
        xpB = __ldcg(xpp + BATCH * HID);
        xpp += 2 * (size_t)BATCH * HID;
    }

    for (int s = 0; s < SEQ; s++) {
        const int cur = s & 1, nxt = cur ^ 1;

        // prefetch xp[s+2] BEFORE the barrier wait (hides DRAM latency)
        float xpC = 0.f;
        if (isrep && s + 2 < SEQ) { xpC = __ldcg(xpp); xpp += (size_t)BATCH * HID; }

        asm volatile("barrier.cluster.wait.aligned;" ::: "memory"); // h(s) ready

        // matvec partials: v[b*4+r] over my 16-element K subset
        float v[8];
#pragma unroll
        for (int b = 0; b < 2; b++) {
            ulonglong2 hc[4];
#pragma unroll
            for (int c = 0; c < 4; c++)
                hc[c] = *(const ulonglong2*)&hs[cur][b][c * 128 + l * 4];
            ull acc[4] = {0ull, 0ull, 0ull, 0ull};
#pragma unroll
            for (int c = 0; c < 4; c++)
#pragma unroll
                for (int r = 0; r < 4; r++) {
                    ffma2(acc[r], wp[r][c][0], hc[c].x);
                    ffma2(acc[r], wp[r][c][1], hc[c].y);
                }
#pragma unroll
            for (int r = 0; r < 4; r++) {
                float2 u = unpk(acc[r]);
                v[b * 4 + r] = u.x + u.y;
            }
        }

        // fold-reduce: 8 values -> 1 per lane (9 shfls total)
        {
            const unsigned FM = 0xffffffffu;
            int hi2 = (l >> 2) & 1;
#pragma unroll
            for (int i = 0; i < 4; i++) {
                float send = hi2 ? v[i] : v[i + 4];
                float recv = __shfl_xor_sync(FM, send, 4);
                v[i] = (hi2 ? v[i + 4] : v[i]) + recv;
            }
            int hi3 = (l >> 3) & 1;
#pragma unroll
            for (int i = 0; i < 2; i++) {
                float send = hi3 ? v[i] : v[i + 2];
                float recv = __shfl_xor_sync(FM, send, 8);
                v[i] = (hi3 ? v[i + 2] : v[i]) + recv;
            }
            int hi4 = (l >> 4) & 1;
            {
                float send = hi4 ? v[0] : v[1];
                float recv = __shfl_xor_sync(FM, send, 16);
                v[0] = (hi4 ? v[1] : v[0]) + recv;
            }
            v[0] += __shfl_xor_sync(FM, v[0], 1);
            v[0] += __shfl_xor_sync(FM, v[0], 2);
        }
        // rep lane holds full sum for (batch brep, row rrep); finish it
        float ft = 0.f;
        if (isrep) ft = ftanh(v[0] + xpA);

        // redistribute to lanes 0..7 as (b = m>>2, r = m&3), then each lane
        // stores the quad-consistent {row0..row3} vector to its 2 peers.
        {
            const unsigned FM = 0xffffffffu;
            int m = l & 7;
            int src = ((m >> 2) << 2) + ((m & 1) << 4) + ((m & 2) << 2);
            float mine = __shfl_sync(FM, ft, src);
            int qb = l & ~3;
            float t0 = __shfl_sync(FM, mine, qb);       // row 0 (FIX: was mine)
            float t1 = __shfl_sync(FM, mine, qb + 1);   // row 1
            float t2 = __shfl_sync(FM, mine, qb + 2);   // row 2
            float t3 = __shfl_sync(FM, mine, qb + 3);   // row 3
            if (l < 8) {
                int b = l >> 2;
                uint32_t boff = (uint32_t)(nxt * 4096 + (b * HID + i0 + w * 4) * 4);
                asm volatile("st.shared::cluster.v4.f32 [%0], {%2, %3, %4, %5};\n\t"
                             "st.shared::cluster.v4.f32 [%1], {%2, %3, %4, %5};"
                             :: "r"(ra0 + boff), "r"(ra1 + boff),
                                "f"(t0), "f"(t1), "f"(t2), "f"(t3) : "memory");
            }
        }

        asm volatile("barrier.cluster.arrive.aligned;" ::: "memory"); // release
        xpA = xpB; xpB = xpC;
    }

    asm volatile("barrier.cluster.wait.aligned;" ::: "memory");       // final

    // hs[0] holds h(SEQ) (SEQ even)
    if (tid < 128) {
        int b = tid >> 6, row = tid & 63;
        g_hfin[(b0 + b) * HID + i0 + row] = hs[0][b][i0 + row];
    }
}

// ---------------------------------------------------------------------------
// Kernel 3: out = h_final @ W_fc^T + b_fc.
// ---------------------------------------------------------------------------
__global__ __launch_bounds__(256) void fc_kernel(
    const float* __restrict__ Wfc, const float* __restrict__ bfc,
    float* __restrict__ out)
{
    __shared__ float hsm[HID];
    const int b = blockIdx.x;
    const int o0 = blockIdx.y * 32;
    const int tid = threadIdx.x;
    for (int i = tid; i < HID; i += 256) hsm[i] = g_hfin[b * HID + i];
    __syncthreads();
    const int w = tid >> 5, l = tid & 31;
#pragma unroll
    for (int oi = 0; oi < 4; oi++) {
        int o = o0 + w * 4 + oi;
        const float* wr = Wfc + (size_t)o * HID;
        float sum = 0.f;
#pragma unroll
        for (int j2 = 0; j2 < HID / 32; j2++)
            sum = fmaf(hsm[j2 * 32 + l], wr[j2 * 32 + l], sum);
#pragma unroll
        for (int off = 16; off > 0; off >>= 1)
            sum += __shfl_down_sync(0xffffffffu, sum, off);
        if (l == 0) out[b * HID + o] = sum + bfc[o];
    }
}

// ---------------------------------------------------------------------------
extern "C" void kernel_launch(void* const* d_in, const int* in_sizes, int n_in,
                              void* d_out, int out_size)
{
    const float* x   = (const float*)d_in[0];
    const float* Wxh = (const float*)d_in[1];
    const float* bxh = (const float*)d_in[2];
    const float* Whh = (const float*)d_in[3];
    const float* bhh = (const float*)d_in[4];
    const float* bh  = (const float*)d_in[5];
    const float* Wfc = (const float*)d_in[6];
    const float* bfc = (const float*)d_in[7];
    float* out = (float*)d_out;

    xproj_gemm<<<dim3(HID / 128, (BATCH * SEQ) / 128), 256>>>(x, Wxh, bxh, bhh, bh);
    scan_kernel<<<128, 512>>>(Whh);
    fc_kernel<<<dim3(BATCH, 16), 256>>>(Wfc, bfc, out);
}

// round 7
// speedup vs baseline: 1.6320x; 1.0403x over previous
#include <cuda_runtime.h>
#include <math.h>
#include <stdint.h>

#define BATCH 32
#define SEQ   2048
#define HID   512

typedef unsigned long long ull;

// Scratch (static device globals: allocation-free)
__device__ float g_xproj[SEQ * BATCH * HID];   // [s][b][h] layout
__device__ float g_hfin[BATCH * HID];          // final hidden state

// ---------------------------------------------------------------------------
// packed f32x2 helpers (FFMA2 only reachable via PTX)
// ---------------------------------------------------------------------------
__device__ __forceinline__ void ffma2(ull& acc, ull a, ull b) {
    asm("fma.rn.f32x2 %0, %1, %2, %0;" : "+l"(acc) : "l"(a), "l"(b));
}
__device__ __forceinline__ ull dup2(float v) {
    ull r; asm("mov.b64 %0, {%1, %1};" : "=l"(r) : "f"(v)); return r;
}
__device__ __forceinline__ float2 unpk(ull v) {
    float2 r; asm("mov.b64 {%0, %1}, %2;" : "=f"(r.x), "=f"(r.y) : "l"(v)); return r;
}
// fast tanh: 1 - 2/(e^{2x}+1); saturates to +-1, no NaN path.
__device__ __forceinline__ float ftanh(float x) {
    float e = __expf(x + x);
    return 1.f - __fdividef(2.f, e + 1.f);
}

// ---------------------------------------------------------------------------
// Kernel 1: xproj = x @ W_xh^T + (b_xh + b_hh + b_h), written as [s][b][h]
// (unchanged: 128x128 tile, FFMA2, reg double-buffer)
// ---------------------------------------------------------------------------
__global__ __launch_bounds__(256, 2) void xproj_gemm(
    const float* __restrict__ X,
    const float* __restrict__ Wxh,
    const float* __restrict__ bxh,
    const float* __restrict__ bhh,
    const float* __restrict__ bh)
{
    __shared__ float As[8][128];
    __shared__ float Bs[8][128];
    const int K = HID;
    const int n0 = blockIdx.x * 128;
    const int m0 = blockIdx.y * 128;
    const int tid = threadIdx.x;

    const int lr = tid >> 1;
    const int lc = (tid & 1) << 2;
    const int ca = (tid & 15) << 2;
    const int ra = (tid >> 4) << 2;

    ull acc[8][4];
#pragma unroll
    for (int i = 0; i < 8; i++)
#pragma unroll
        for (int j = 0; j < 4; j++) acc[i][j] = 0ull;

    const float* Aptr = X   + (size_t)(m0 + lr) * K + lc;
    const float* Bptr = Wxh + (size_t)(n0 + lr) * K + lc;

    float4 a4 = *(const float4*)(Aptr);
    float4 b4 = *(const float4*)(Bptr);

    for (int k0 = 0; k0 < K; k0 += 8) {
        As[lc + 0][lr] = a4.x; As[lc + 1][lr] = a4.y;
        As[lc + 2][lr] = a4.z; As[lc + 3][lr] = a4.w;
        Bs[lc + 0][lr] = b4.x; Bs[lc + 1][lr] = b4.y;
        Bs[lc + 2][lr] = b4.z; Bs[lc + 3][lr] = b4.w;
        __syncthreads();
        if (k0 + 8 < K) {
            a4 = *(const float4*)(Aptr + k0 + 8);
            b4 = *(const float4*)(Bptr + k0 + 8);
        }
#pragma unroll
        for (int k = 0; k < 8; k++) {
            float am[8];
            *(float4*)&am[0] = *(const float4*)&As[k][ra];
            *(float4*)&am[4] = *(const float4*)&As[k][ra + 64];
            ulonglong2 b01 = *(const ulonglong2*)&Bs[k][ca];
            ulonglong2 b23 = *(const ulonglong2*)&Bs[k][ca + 64];
#pragma unroll
            for (int i = 0; i < 8; i++) {
                ull ad = dup2(am[i]);
                ffma2(acc[i][0], ad, b01.x);
                ffma2(acc[i][1], ad, b01.y);
                ffma2(acc[i][2], ad, b23.x);
                ffma2(acc[i][3], ad, b23.y);
            }
        }
        __syncthreads();
    }

    float biasv[8];
#pragma unroll
    for (int j = 0; j < 8; j++) {
        int n = n0 + ((j < 4) ? (ca + j) : (64 + ca + j - 4));
        biasv[j] = bxh[n] + bhh[n] + bh[n];
    }

#pragma unroll
    for (int i = 0; i < 8; i++) {
        int m = m0 + ((i < 4) ? (ra + i) : (64 + ra + i - 4));
        int b = m >> 11;
        int s = m & (SEQ - 1);
        float* outr = &g_xproj[((size_t)s * BATCH + b) * HID + n0];
        float2 p0 = unpk(acc[i][0]);
        float2 p1 = unpk(acc[i][1]);
        float2 p2 = unpk(acc[i][2]);
        float2 p3 = unpk(acc[i][3]);
        float4 v0, v1;
        v0.x = p0.x + biasv[0]; v0.y = p0.y + biasv[1];
        v0.z = p1.x + biasv[2]; v0.w = p1.y + biasv[3];
        v1.x = p2.x + biasv[4]; v1.y = p2.y + biasv[5];
        v1.z = p3.x + biasv[6]; v1.w = p3.y + biasv[7];
        *(float4*)&outr[ca]      = v0;
        *(float4*)&outr[64 + ca] = v1;
    }
}

// ---------------------------------------------------------------------------
// Kernel 2: persistent recurrent scan. 16 clusters x 8 CTAs; cluster = 2
// batches, CTA rank = 64 hidden rows. Compute/marshal identical to R6
// (registers-only weights, fold+butterfly shfl reduce). Exchange/sync:
// st.async remote stores with mbarrier complete_tx byte accounting — data
// goes registers -> all 8 peers' hs[nxt]; the tx-count mbarrier (4096 B =
// full h for 2 batches) IS the barrier. No cluster barrier, no fences, no
// __syncthreads in the loop; warps free-run and sleep on try_wait.
// ---------------------------------------------------------------------------
__global__ __launch_bounds__(512, 1) __cluster_dims__(8, 1, 1)
void scan_kernel(const float* __restrict__ Whh)
{
    __shared__ __align__(16) float hs[2][2][HID];   // [buf][batch][k]  8KB
    __shared__ __align__(8) ull fullmb[2];          // tx mbarrier per buffer

    const int tid = threadIdx.x;
    const int w = tid >> 5, l = tid & 31;

    unsigned rank;
    asm("mov.u32 %0, %%cluster_ctarank;" : "=r"(rank));
    const int b0 = (int)(blockIdx.x >> 3) * 2;
    const int i0 = (int)rank * 64;

    // Weights: rows i0+w*4+r, k = c*128 + l*4 + {0..3}, as f32x2 pairs.
    ull wp[4][4][2];
#pragma unroll
    for (int r = 0; r < 4; r++)
#pragma unroll
        for (int c = 0; c < 4; c++) {
            ulonglong2 u = *(const ulonglong2*)
                (&Whh[(size_t)(i0 + w * 4 + r) * HID + c * 128 + l * 4]);
            wp[r][c][0] = u.x; wp[r][c][1] = u.y;
        }

    // mapa'd peer addresses (data base + mbarrier base), lanes 0..7 cover
    // peers 2(l&3) and 2(l&3)+1.
    uint32_t hbase  = (uint32_t)__cvta_generic_to_shared(&hs[0][0][0]);
    uint32_t mbbase = (uint32_t)__cvta_generic_to_shared(&fullmb[0]);
    uint32_t lmb[2];
    lmb[0] = mbbase; lmb[1] = mbbase + 8;
    uint32_t ra0 = 0, ra1 = 0, rm0 = 0, rm1 = 0;
    if (l < 8) {
        int p0 = (l & 3) * 2;
        asm("mapa.shared::cluster.u32 %0, %1, %2;" : "=r"(ra0) : "r"(hbase), "r"(p0));
        asm("mapa.shared::cluster.u32 %0, %1, %2;" : "=r"(ra1) : "r"(hbase), "r"(p0 + 1));
        asm("mapa.shared::cluster.u32 %0, %1, %2;" : "=r"(rm0) : "r"(mbbase), "r"(p0));
        asm("mapa.shared::cluster.u32 %0, %1, %2;" : "=r"(rm1) : "r"(mbbase), "r"(p0 + 1));
    }

    // rep lanes (l%4==0) own (batch brep, row w*4+rrep) after the fold-reduce
    const int brep = (l >> 2) & 1;
    const int rrep = ((l >> 3) & 1) * 2 + ((l >> 4) & 1);
    const bool isrep = ((l & 3) == 0);

    // Init: h(0)=0, mbarriers count=1, pre-arm full[1] for iteration-0 stores.
    for (int i = tid; i < 2 * HID; i += 512) ((float*)hs[0])[i] = 0.f;
    if (tid == 0) {
        asm volatile("mbarrier.init.shared.b64 [%0], %1;" :: "r"(lmb[0]), "r"(1u) : "memory");
        asm volatile("mbarrier.init.shared.b64 [%0], %1;" :: "r"(lmb[1]), "r"(1u) : "memory");
        asm volatile("mbarrier.arrive.expect_tx.shared::cta.b64 _, [%0], %1;"
                     :: "r"(lmb[1]), "r"(4096u) : "memory");
    }
    __syncthreads();
    asm volatile("barrier.cluster.arrive.aligned;" ::: "memory");
    asm volatile("barrier.cluster.wait.aligned;" ::: "memory");

    int pb0 = 0, pb1 = 0;   // wait parity per buffer

    // xproj prefetch ring, 2 deep, on rep lanes
    const float* xpp = &g_xproj[(size_t)(b0 + brep) * HID + i0 + w * 4 + rrep];
    float xpA = 0.f, xpB = 0.f;
    if (isrep) {
        xpA = __ldcg(xpp);
        xpB = __ldcg(xpp + BATCH * HID);
        xpp += 2 * (size_t)BATCH * HID;
    }

    for (int s = 0; s < SEQ; s++) {
        const int cur = s & 1, nxt = cur ^ 1;
        const uint32_t mbc = (cur == 0) ? lmb[0] : lmb[1];

        // prefetch xp[s+2] BEFORE the wait (hides DRAM latency)
        float xpC = 0.f;
        if (isrep && s + 2 < SEQ) { xpC = __ldcg(xpp); xpp += (size_t)BATCH * HID; }

        // wait h(s) byte-complete (s==0: local zeros, no wait)
        if (s > 0) {
            uint32_t P = (uint32_t)((cur == 0) ? pb0 : pb1);
            asm volatile(
                "{\n\t.reg .pred p;\n\t"
                "W%=:\n\t"
                "mbarrier.try_wait.parity.acquire.cta.shared::cta.b64 p, [%0], %1, 0x989680;\n\t"
                "@!p bra W%=;\n\t}"
                :: "r"(mbc), "r"(P) : "memory");
            if (cur == 0) pb0 ^= 1; else pb1 ^= 1;
        }
        // re-arm full[cur] for its next delivery (iteration s+1's stores)
        if (tid == 0)
            asm volatile("mbarrier.arrive.expect_tx.shared::cta.b64 _, [%0], %1;"
                         :: "r"(mbc), "r"(4096u) : "memory");

        // matvec partials: v[b*4+r] over my 16-element K subset
        float v[8];
#pragma unroll
        for (int b = 0; b < 2; b++) {
            ulonglong2 hc[4];
#pragma unroll
            for (int c = 0; c < 4; c++)
                hc[c] = *(const ulonglong2*)&hs[cur][b][c * 128 + l * 4];
            ull acc[4] = {0ull, 0ull, 0ull, 0ull};
#pragma unroll
            for (int c = 0; c < 4; c++)
#pragma unroll
                for (int r = 0; r < 4; r++) {
                    ffma2(acc[r], wp[r][c][0], hc[c].x);
                    ffma2(acc[r], wp[r][c][1], hc[c].y);
                }
#pragma unroll
            for (int r = 0; r < 4; r++) {
                float2 u = unpk(acc[r]);
                v[b * 4 + r] = u.x + u.y;
            }
        }

        // fold-reduce: 8 values -> 1 per lane (9 shfls total)
        {
            const unsigned FM = 0xffffffffu;
            int hi2 = (l >> 2) & 1;
#pragma unroll
            for (int i = 0; i < 4; i++) {
                float send = hi2 ? v[i] : v[i + 4];
                float recv = __shfl_xor_sync(FM, send, 4);
                v[i] = (hi2 ? v[i + 4] : v[i]) + recv;
            }
            int hi3 = (l >> 3) & 1;
#pragma unroll
            for (int i = 0; i < 2; i++) {
                float send = hi3 ? v[i] : v[i + 2];
                float recv = __shfl_xor_sync(FM, send, 8);
                v[i] = (hi3 ? v[i + 2] : v[i]) + recv;
            }
            int hi4 = (l >> 4) & 1;
            {
                float send = hi4 ? v[0] : v[1];
                float recv = __shfl_xor_sync(FM, send, 16);
                v[0] = (hi4 ? v[1] : v[0]) + recv;
            }
            v[0] += __shfl_xor_sync(FM, v[0], 1);
            v[0] += __shfl_xor_sync(FM, v[0], 2);
        }
        float ft = 0.f;
        if (isrep) ft = ftanh(v[0] + xpA);

        // redistribute to lanes 0..7 as (b = m>>2, r = m&3); quad-consistent
        // v4 {row0..row3}; each lane st.asyncs 16B to its 2 peers.
        {
            const unsigned FM = 0xffffffffu;
            int m = l & 7;
            int src = ((m >> 2) << 2) + ((m & 1) << 4) + ((m & 2) << 2);
            float mine = __shfl_sync(FM, ft, src);
            int qb = l & ~3;
            float t0 = __shfl_sync(FM, mine, qb);
            float t1 = __shfl_sync(FM, mine, qb + 1);
            float t2 = __shfl_sync(FM, mine, qb + 2);
            float t3 = __shfl_sync(FM, mine, qb + 3);
            if (l < 8) {
                int b = l >> 2;
                uint32_t boff = (uint32_t)(nxt * 4096 + (b * HID + i0 + w * 4) * 4);
                ull lo, hi;
                asm("mov.b64 %0, {%1, %2};" : "=l"(lo) : "f"(t0), "f"(t1));
                asm("mov.b64 %0, {%1, %2};" : "=l"(hi) : "f"(t2), "f"(t3));
                uint32_t rmb0 = rm0 + (uint32_t)(nxt * 8);
                uint32_t rmb1 = rm1 + (uint32_t)(nxt * 8);
                asm volatile(
                    "st.async.shared::cluster.mbarrier::complete_tx::bytes.b64 [%0], %2, [%4];\n\t"
                    "st.async.shared::cluster.mbarrier::complete_tx::bytes.b64 [%1], %3, [%4];"
                    :: "r"(ra0 + boff), "r"(ra0 + boff + 8), "l"(lo), "l"(hi), "r"(rmb0)
                    : "memory");
                asm volatile(
                    "st.async.shared::cluster.mbarrier::complete_tx::bytes.b64 [%0], %2, [%4];\n\t"
                    "st.async.shared::cluster.mbarrier::complete_tx::bytes.b64 [%1], %3, [%4];"
                    :: "r"(ra1 + boff), "r"(ra1 + boff + 8), "l"(lo), "l"(hi), "r"(rmb1)
                    : "memory");
            }
        }
        xpA = xpB; xpB = xpC;
    }

    // final: h(SEQ) lands in hs[0] (SEQ even) under full[0]
    {
        asm volatile(
            "{\n\t.reg .pred p;\n\t"
            "W%=:\n\t"
            "mbarrier.try_wait.parity.acquire.cta.shared::cta.b64 p, [%0], %1, 0x989680;\n\t"
            "@!p bra W%=;\n\t}"
            :: "r"(lmb[0]), "r"((uint32_t)pb0) : "memory");
    }
    if (tid < 128) {
        int b = tid >> 6, row = tid & 63;
        g_hfin[(b0 + b) * HID + i0 + row] = hs[0][b][i0 + row];
    }
}

// ---------------------------------------------------------------------------
// Kernel 3: out = h_final @ W_fc^T + b_fc.
// ---------------------------------------------------------------------------
__global__ __launch_bounds__(256) void fc_kernel(
    const float* __restrict__ Wfc, const float* __restrict__ bfc,
    float* __restrict__ out)
{
    __shared__ float hsm[HID];
    const int b = blockIdx.x;
    const int o0 = blockIdx.y * 32;
    const int tid = threadIdx.x;
    for (int i = tid; i < HID; i += 256) hsm[i] = g_hfin[b * HID + i];
    __syncthreads();
    const int w = tid >> 5, l = tid & 31;
#pragma unroll
    for (int oi = 0; oi < 4; oi++) {
        int o = o0 + w * 4 + oi;
        const float* wr = Wfc + (size_t)o * HID;
        float sum = 0.f;
#pragma unroll
        for (int j2 = 0; j2 < HID / 32; j2++)
            sum = fmaf(hsm[j2 * 32 + l], wr[j2 * 32 + l], sum);
#pragma unroll
        for (int off = 16; off > 0; off >>= 1)
            sum += __shfl_down_sync(0xffffffffu, sum, off);
        if (l == 0) out[b * HID + o] = sum + bfc[o];
    }
}

// ---------------------------------------------------------------------------
extern "C" void kernel_launch(void* const* d_in, const int* in_sizes, int n_in,
                              void* d_out, int out_size)
{
    const float* x   = (const float*)d_in[0];
    const float* Wxh = (const float*)d_in[1];
    const float* bxh = (const float*)d_in[2];
    const float* Whh = (const float*)d_in[3];
    const float* bhh = (const float*)d_in[4];
    const float* bh  = (const float*)d_in[5];
    const float* Wfc = (const float*)d_in[6];
    const float* bfc = (const float*)d_in[7];
    float* out = (float*)d_out;

    xproj_gemm<<<dim3(HID / 128, (BATCH * SEQ) / 128), 256>>>(x, Wxh, bxh, bhh, bh);
    scan_kernel<<<128, 512>>>(Whh);
    fc_kernel<<<dim3(BATCH, 16), 256>>>(Wfc, bfc, out);
}

// round 8
// speedup vs baseline: 1.8263x; 1.1191x over previous
#include <cuda_runtime.h>
#include <math.h>
#include <stdint.h>

#define BATCH 32
#define SEQ   2048
#define HID   512

typedef unsigned long long ull;

// Scratch (static device globals: allocation-free)
__device__ float g_xproj[SEQ * BATCH * HID];   // [s][b][h] layout
__device__ float g_hfin[BATCH * HID];          // final hidden state

// ---------------------------------------------------------------------------
// packed f32x2 helpers (FFMA2 only reachable via PTX)
// ---------------------------------------------------------------------------
__device__ __forceinline__ void ffma2(ull& acc, ull a, ull b) {
    asm("fma.rn.f32x2 %0, %1, %2, %0;" : "+l"(acc) : "l"(a), "l"(b));
}
__device__ __forceinline__ ull dup2(float v) {
    ull r; asm("mov.b64 %0, {%1, %1};" : "=l"(r) : "f"(v)); return r;
}
__device__ __forceinline__ float2 unpk(ull v) {
    float2 r; asm("mov.b64 {%0, %1}, %2;" : "=f"(r.x), "=f"(r.y) : "l"(v)); return r;
}
// fast tanh: 1 - 2/(e^{2x}+1); saturates to +-1, no NaN path.
__device__ __forceinline__ float ftanh(float x) {
    float e = __expf(x + x);
    return 1.f - __fdividef(2.f, e + 1.f);
}

// ---------------------------------------------------------------------------
// Kernel 1: xproj = x @ W_xh^T + (b_xh + b_hh + b_h), written as [s][b][h]
// (unchanged: 128x128 tile, FFMA2, reg double-buffer)
// ---------------------------------------------------------------------------
__global__ __launch_bounds__(256, 2) void xproj_gemm(
    const float* __restrict__ X,
    const float* __restrict__ Wxh,
    const float* __restrict__ bxh,
    const float* __restrict__ bhh,
    const float* __restrict__ bh)
{
    __shared__ float As[8][128];
    __shared__ float Bs[8][128];
    const int K = HID;
    const int n0 = blockIdx.x * 128;
    const int m0 = blockIdx.y * 128;
    const int tid = threadIdx.x;

    const int lr = tid >> 1;
    const int lc = (tid & 1) << 2;
    const int ca = (tid & 15) << 2;
    const int ra = (tid >> 4) << 2;

    ull acc[8][4];
#pragma unroll
    for (int i = 0; i < 8; i++)
#pragma unroll
        for (int j = 0; j < 4; j++) acc[i][j] = 0ull;

    const float* Aptr = X   + (size_t)(m0 + lr) * K + lc;
    const float* Bptr = Wxh + (size_t)(n0 + lr) * K + lc;

    float4 a4 = *(const float4*)(Aptr);
    float4 b4 = *(const float4*)(Bptr);

    for (int k0 = 0; k0 < K; k0 += 8) {
        As[lc + 0][lr] = a4.x; As[lc + 1][lr] = a4.y;
        As[lc + 2][lr] = a4.z; As[lc + 3][lr] = a4.w;
        Bs[lc + 0][lr] = b4.x; Bs[lc + 1][lr] = b4.y;
        Bs[lc + 2][lr] = b4.z; Bs[lc + 3][lr] = b4.w;
        __syncthreads();
        if (k0 + 8 < K) {
            a4 = *(const float4*)(Aptr + k0 + 8);
            b4 = *(const float4*)(Bptr + k0 + 8);
        }
#pragma unroll
        for (int k = 0; k < 8; k++) {
            float am[8];
            *(float4*)&am[0] = *(const float4*)&As[k][ra];
            *(float4*)&am[4] = *(const float4*)&As[k][ra + 64];
            ulonglong2 b01 = *(const ulonglong2*)&Bs[k][ca];
            ulonglong2 b23 = *(const ulonglong2*)&Bs[k][ca + 64];
#pragma unroll
            for (int i = 0; i < 8; i++) {
                ull ad = dup2(am[i]);
                ffma2(acc[i][0], ad, b01.x);
                ffma2(acc[i][1], ad, b01.y);
                ffma2(acc[i][2], ad, b23.x);
                ffma2(acc[i][3], ad, b23.y);
            }
        }
        __syncthreads();
    }

    float biasv[8];
#pragma unroll
    for (int j = 0; j < 8; j++) {
        int n = n0 + ((j < 4) ? (ca + j) : (64 + ca + j - 4));
        biasv[j] = bxh[n] + bhh[n] + bh[n];
    }

#pragma unroll
    for (int i = 0; i < 8; i++) {
        int m = m0 + ((i < 4) ? (ra + i) : (64 + ra + i - 4));
        int b = m >> 11;
        int s = m & (SEQ - 1);
        float* outr = &g_xproj[((size_t)s * BATCH + b) * HID + n0];
        float2 p0 = unpk(acc[i][0]);
        float2 p1 = unpk(acc[i][1]);
        float2 p2 = unpk(acc[i][2]);
        float2 p3 = unpk(acc[i][3]);
        float4 v0, v1;
        v0.x = p0.x + biasv[0]; v0.y = p0.y + biasv[1];
        v0.z = p1.x + biasv[2]; v0.w = p1.y + biasv[3];
        v1.x = p2.x + biasv[4]; v1.y = p2.y + biasv[5];
        v1.z = p3.x + biasv[6]; v1.w = p3.y + biasv[7];
        *(float4*)&outr[ca]      = v0;
        *(float4*)&outr[64 + ca] = v1;
    }
}

// ---------------------------------------------------------------------------
// Kernel 2: persistent recurrent scan. 16 clusters x 8 CTAs; cluster = 2
// batches, CTA rank = 64 hidden rows. Weights in RF; fold+butterfly shfl
// reduce. h layout [buf][rank][batch][64] so each producer's slice is one
// contiguous 512B chunk. Exchange: reps STS into parity-buffered staging, one
// bar.sync, then warp0 lanes 0-7 issue ONE 512B cp.async.bulk per peer with
// remote complete_tx — 8 tx events per consumer per step (was 128).
// ---------------------------------------------------------------------------
__global__ __launch_bounds__(512, 1) __cluster_dims__(8, 1, 1)
void scan_kernel(const float* __restrict__ Whh)
{
    __shared__ __align__(16) float hs[2][8][2][64];  // [buf][rank][batch][row] 8KB
    __shared__ __align__(16) float outs[2][2][64];   // [parity][batch][row] 1KB
    __shared__ __align__(8) ull fullmb[2];           // tx mbarrier per buffer

    const int tid = threadIdx.x;
    const int w = tid >> 5, l = tid & 31;

    unsigned rank;
    asm("mov.u32 %0, %%cluster_ctarank;" : "=r"(rank));
    const int b0 = (int)(blockIdx.x >> 3) * 2;
    const int i0 = (int)rank * 64;

    // Weights: rows i0+w*4+r, k = c*128 + l*4 + {0..3}, as f32x2 pairs.
    ull wp[4][4][2];
#pragma unroll
    for (int r = 0; r < 4; r++)
#pragma unroll
        for (int c = 0; c < 4; c++) {
            ulonglong2 u = *(const ulonglong2*)
                (&Whh[(size_t)(i0 + w * 4 + r) * HID + c * 128 + l * 4]);
            wp[r][c][0] = u.x; wp[r][c][1] = u.y;
        }

    uint32_t hbase  = (uint32_t)__cvta_generic_to_shared(&hs[0][0][0][0]);
    uint32_t mbbase = (uint32_t)__cvta_generic_to_shared(&fullmb[0]);
    uint32_t srcb   = (uint32_t)__cvta_generic_to_shared(&outs[0][0][0]);
    uint32_t lmb[2];
    lmb[0] = mbbase; lmb[1] = mbbase + 8;

    // warp0 lanes 0-7: peer l's copy of MY slice + peer l's mbarrier.
    uint32_t rdst = 0, rmb = 0;
    if (w == 0 && l < 8) {
        uint32_t myslice = hbase + (uint32_t)(rank * 512); // &hs[0][rank][0][0]
        asm("mapa.shared::cluster.u32 %0, %1, %2;" : "=r"(rdst) : "r"(myslice), "r"(l));
        asm("mapa.shared::cluster.u32 %0, %1, %2;" : "=r"(rmb)  : "r"(mbbase), "r"(l));
    }

    // rep lanes (l%4==0) own (batch brep, row w*4+rrep) after the fold-reduce
    const int brep = (l >> 2) & 1;
    const int rrep = ((l >> 3) & 1) * 2 + ((l >> 4) & 1);
    const bool isrep = ((l & 3) == 0);

    // Init: h(0)=0, mbarriers count=1, pre-arm full[1] for iteration-0 copies.
    for (int i = tid; i < 2 * HID; i += 512) ((float*)hs[0])[i] = 0.f;
    if (tid == 0) {
        asm volatile("mbarrier.init.shared.b64 [%0], %1;" :: "r"(lmb[0]), "r"(1u) : "memory");
        asm volatile("mbarrier.init.shared.b64 [%0], %1;" :: "r"(lmb[1]), "r"(1u) : "memory");
        asm volatile("mbarrier.arrive.expect_tx.shared::cta.b64 _, [%0], %1;"
                     :: "r"(lmb[1]), "r"(4096u) : "memory");
    }
    __syncthreads();
    asm volatile("barrier.cluster.arrive.aligned;" ::: "memory");
    asm volatile("barrier.cluster.wait.aligned;" ::: "memory");

    int pb0 = 0, pb1 = 0;   // wait parity per buffer

    // xproj prefetch ring, 2 deep, on rep lanes
    const float* xpp = &g_xproj[(size_t)(b0 + brep) * HID + i0 + w * 4 + rrep];
    float xpA = 0.f, xpB = 0.f;
    if (isrep) {
        xpA = __ldcg(xpp);
        xpB = __ldcg(xpp + BATCH * HID);
        xpp += 2 * (size_t)BATCH * HID;
    }

    // per-lane base offset into hs slab: h[b][k] = hb[c*256 + b*64]
    const int lbase = (l >> 4) * 128 + (l & 15) * 4;

    for (int s = 0; s < SEQ; s++) {
        const int cur = s & 1, nxt = cur ^ 1;
        const uint32_t mbc = (cur == 0) ? lmb[0] : lmb[1];

        // prefetch xp[s+2] BEFORE the wait (hides DRAM latency)
        float xpC = 0.f;
        if (isrep && s + 2 < SEQ) { xpC = __ldcg(xpp); xpp += (size_t)BATCH * HID; }

        // wait h(s) byte-complete (s==0: local zeros, no wait)
        if (s > 0) {
            uint32_t P = (uint32_t)((cur == 0) ? pb0 : pb1);
            asm volatile(
                "{\n\t.reg .pred p;\n\t"
                "W%=:\n\t"
                "mbarrier.try_wait.parity.acquire.cta.shared::cta.b64 p, [%0], %1, 0x989680;\n\t"
                "@!p bra W%=;\n\t}"
                :: "r"(mbc), "r"(P) : "memory");
            if (cur == 0) pb0 ^= 1; else pb1 ^= 1;
        }
        // re-arm full[cur] for its next delivery (iteration s+1's copies)
        if (tid == 0)
            asm volatile("mbarrier.arrive.expect_tx.shared::cta.b64 _, [%0], %1;"
                         :: "r"(mbc), "r"(4096u) : "memory");

        // matvec partials: v[b*4+r] over my 16-element K subset
        const float* hb = &hs[cur][0][0][0] + lbase;
        float v[8];
#pragma unroll
        for (int b = 0; b < 2; b++) {
            ulonglong2 hc[4];
#pragma unroll
            for (int c = 0; c < 4; c++)
                hc[c] = *(const ulonglong2*)(hb + c * 256 + b * 64);
            ull acc[4] = {0ull, 0ull, 0ull, 0ull};
#pragma unroll
            for (int c = 0; c < 4; c++)
#pragma unroll
                for (int r = 0; r < 4; r++) {
                    ffma2(acc[r], wp[r][c][0], hc[c].x);
                    ffma2(acc[r], wp[r][c][1], hc[c].y);
                }
#pragma unroll
            for (int r = 0; r < 4; r++) {
                float2 u = unpk(acc[r]);
                v[b * 4 + r] = u.x + u.y;
            }
        }

        // fold-reduce: 8 values -> 1 per lane (9 shfls total)
        {
            const unsigned FM = 0xffffffffu;
            int hi2 = (l >> 2) & 1;
#pragma unroll
            for (int i = 0; i < 4; i++) {
                float send = hi2 ? v[i] : v[i + 4];
                float recv = __shfl_xor_sync(FM, send, 4);
                v[i] = (hi2 ? v[i + 4] : v[i]) + recv;
            }
            int hi3 = (l >> 3) & 1;
#pragma unroll
            for (int i = 0; i < 2; i++) {
                float send = hi3 ? v[i] : v[i + 2];
                float recv = __shfl_xor_sync(FM, send, 8);
                v[i] = (hi3 ? v[i + 2] : v[i]) + recv;
            }
            int hi4 = (l >> 4) & 1;
            {
                float send = hi4 ? v[0] : v[1];
                float recv = __shfl_xor_sync(FM, send, 16);
                v[0] = (hi4 ? v[1] : v[0]) + recv;
            }
            v[0] += __shfl_xor_sync(FM, v[0], 1);
            v[0] += __shfl_xor_sync(FM, v[0], 2);
        }
        // rep lanes finish their output and stage it locally
        if (isrep)
            outs[cur][brep][w * 4 + rrep] = ftanh(v[0] + xpA);
        __syncthreads();

        // warp0 lanes 0-7: one 512B bulk copy of my slice to peer l
        if (w == 0 && l < 8) {
            asm volatile("fence.proxy.async.shared::cta;" ::: "memory");
            asm volatile(
                "cp.async.bulk.shared::cluster.shared::cta.mbarrier::complete_tx::bytes"
                " [%0], [%1], %2, [%3];"
                :: "r"(rdst + (uint32_t)(nxt * 4096)),
                   "r"(srcb + (uint32_t)(cur * 512)),
                   "r"(512u),
                   "r"(rmb + (uint32_t)(nxt * 8))
                : "memory");
        }
        xpA = xpB; xpB = xpC;
    }

    // final: h(SEQ) lands in hs[0] (SEQ even) under full[0]
    asm volatile(
        "{\n\t.reg .pred p;\n\t"
        "W%=:\n\t"
        "mbarrier.try_wait.parity.acquire.cta.shared::cta.b64 p, [%0], %1, 0x989680;\n\t"
        "@!p bra W%=;\n\t}"
        :: "r"(lmb[0]), "r"((uint32_t)pb0) : "memory");

    for (int idx = tid; idx < 2 * HID; idx += 512) {
        int b = idx >> 9;          // 0..1
        int k = idx & 511;         // 0..511
        g_hfin[(b0 + b) * HID + k] = hs[0][k >> 6][b][k & 63];
    }
}

// ---------------------------------------------------------------------------
// Kernel 3: out = h_final @ W_fc^T + b_fc.
// ---------------------------------------------------------------------------
__global__ __launch_bounds__(256) void fc_kernel(
    const float* __restrict__ Wfc, const float* __restrict__ bfc,
    float* __restrict__ out)
{
    __shared__ float hsm[HID];
    const int b = blockIdx.x;
    const int o0 = blockIdx.y * 32;
    const int tid = threadIdx.x;
    for (int i = tid; i < HID; i += 256) hsm[i] = g_hfin[b * HID + i];
    __syncthreads();
    const int w = tid >> 5, l = tid & 31;
#pragma unroll
    for (int oi = 0; oi < 4; oi++) {
        int o = o0 + w * 4 + oi;
        const float* wr = Wfc + (size_t)o * HID;
        float sum = 0.f;
#pragma unroll
        for (int j2 = 0; j2 < HID / 32; j2++)
            sum = fmaf(hsm[j2 * 32 + l], wr[j2 * 32 + l], sum);
#pragma unroll
        for (int off = 16; off > 0; off >>= 1)
            sum += __shfl_down_sync(0xffffffffu, sum, off);
        if (l == 0) out[b * HID + o] = sum + bfc[o];
    }
}

// ---------------------------------------------------------------------------
extern "C" void kernel_launch(void* const* d_in, const int* in_sizes, int n_in,
                              void* d_out, int out_size)
{
    const float* x   = (const float*)d_in[0];
    const float* Wxh = (const float*)d_in[1];
    const float* bxh = (const float*)d_in[2];
    const float* Whh = (const float*)d_in[3];
    const float* bhh = (const float*)d_in[4];
    const float* bh  = (const float*)d_in[5];
    const float* Wfc = (const float*)d_in[6];
    const float* bfc = (const float*)d_in[7];
    float* out = (float*)d_out;

    xproj_gemm<<<dim3(HID / 128, (BATCH * SEQ) / 128), 256>>>(x, Wxh, bxh, bhh, bh);
    scan_kernel<<<128, 512>>>(Whh);
    fc_kernel<<<dim3(BATCH, 16), 256>>>(Wfc, bfc, out);
}

// round 9
// speedup vs baseline: 1.9650x; 1.0759x over previous
#include <cuda_runtime.h>
#include <math.h>
#include <stdint.h>

#define BATCH 32
#define SEQ   2048
#define HID   512

typedef unsigned long long ull;

// Scratch (static device globals: allocation-free)
__device__ float g_xproj[SEQ * BATCH * HID];   // [s][b][h] layout
__device__ float g_hfin[BATCH * HID];          // final hidden state

// ---------------------------------------------------------------------------
// packed f32x2 helpers (FFMA2 only reachable via PTX)
// ---------------------------------------------------------------------------
__device__ __forceinline__ void ffma2(ull& acc, ull a, ull b) {
    asm("fma.rn.f32x2 %0, %1, %2, %0;" : "+l"(acc) : "l"(a), "l"(b));
}
__device__ __forceinline__ ull dup2(float v) {
    ull r; asm("mov.b64 %0, {%1, %1};" : "=l"(r) : "f"(v)); return r;
}
__device__ __forceinline__ float2 unpk(ull v) {
    float2 r; asm("mov.b64 {%0, %1}, %2;" : "=f"(r.x), "=f"(r.y) : "l"(v)); return r;
}
// fast tanh: 1 - 2/(e^{2x}+1); saturates to +-1, no NaN path.
__device__ __forceinline__ float ftanh(float x) {
    float e = __expf(x + x);
    return 1.f - __fdividef(2.f, e + 1.f);
}

// ---------------------------------------------------------------------------
// Kernel 1: xproj = x @ W_xh^T + (b_xh + b_hh + b_h), written as [s][b][h]
// (unchanged: 128x128 tile, FFMA2, reg double-buffer)
// ---------------------------------------------------------------------------
__global__ __launch_bounds__(256, 2) void xproj_gemm(
    const float* __restrict__ X,
    const float* __restrict__ Wxh,
    const float* __restrict__ bxh,
    const float* __restrict__ bhh,
    const float* __restrict__ bh)
{
    __shared__ float As[8][128];
    __shared__ float Bs[8][128];
    const int K = HID;
    const int n0 = blockIdx.x * 128;
    const int m0 = blockIdx.y * 128;
    const int tid = threadIdx.x;

    const int lr = tid >> 1;
    const int lc = (tid & 1) << 2;
    const int ca = (tid & 15) << 2;
    const int ra = (tid >> 4) << 2;

    ull acc[8][4];
#pragma unroll
    for (int i = 0; i < 8; i++)
#pragma unroll
        for (int j = 0; j < 4; j++) acc[i][j] = 0ull;

    const float* Aptr = X   + (size_t)(m0 + lr) * K + lc;
    const float* Bptr = Wxh + (size_t)(n0 + lr) * K + lc;

    float4 a4 = *(const float4*)(Aptr);
    float4 b4 = *(const float4*)(Bptr);

    for (int k0 = 0; k0 < K; k0 += 8) {
        As[lc + 0][lr] = a4.x; As[lc + 1][lr] = a4.y;
        As[lc + 2][lr] = a4.z; As[lc + 3][lr] = a4.w;
        Bs[lc + 0][lr] = b4.x; Bs[lc + 1][lr] = b4.y;
        Bs[lc + 2][lr] = b4.z; Bs[lc + 3][lr] = b4.w;
        __syncthreads();
        if (k0 + 8 < K) {
            a4 = *(const float4*)(Aptr + k0 + 8);
            b4 = *(const float4*)(Bptr + k0 + 8);
        }
#pragma unroll
        for (int k = 0; k < 8; k++) {
            float am[8];
            *(float4*)&am[0] = *(const float4*)&As[k][ra];
            *(float4*)&am[4] = *(const float4*)&As[k][ra + 64];
            ulonglong2 b01 = *(const ulonglong2*)&Bs[k][ca];
            ulonglong2 b23 = *(const ulonglong2*)&Bs[k][ca + 64];
#pragma unroll
            for (int i = 0; i < 8; i++) {
                ull ad = dup2(am[i]);
                ffma2(acc[i][0], ad, b01.x);
                ffma2(acc[i][1], ad, b01.y);
                ffma2(acc[i][2], ad, b23.x);
                ffma2(acc[i][3], ad, b23.y);
            }
        }
        __syncthreads();
    }

    float biasv[8];
#pragma unroll
    for (int j = 0; j < 8; j++) {
        int n = n0 + ((j < 4) ? (ca + j) : (64 + ca + j - 4));
        biasv[j] = bxh[n] + bhh[n] + bh[n];
    }

#pragma unroll
    for (int i = 0; i < 8; i++) {
        int m = m0 + ((i < 4) ? (ra + i) : (64 + ra + i - 4));
        int b = m >> 11;
        int s = m & (SEQ - 1);
        float* outr = &g_xproj[((size_t)s * BATCH + b) * HID + n0];
        float2 p0 = unpk(acc[i][0]);
        float2 p1 = unpk(acc[i][1]);
        float2 p2 = unpk(acc[i][2]);
        float2 p3 = unpk(acc[i][3]);
        float4 v0, v1;
        v0.x = p0.x + biasv[0]; v0.y = p0.y + biasv[1];
        v0.z = p1.x + biasv[2]; v0.w = p1.y + biasv[3];
        v1.x = p2.x + biasv[4]; v1.y = p2.y + biasv[5];
        v1.z = p3.x + biasv[6]; v1.w = p3.y + biasv[7];
        *(float4*)&outr[ca]      = v0;
        *(float4*)&outr[64 + ca] = v1;
    }
}

// ---------------------------------------------------------------------------
// Kernel 2: persistent recurrent scan. 16 clusters x 8 CTAs; cluster = 2
// batches, CTA rank = 64 hidden rows. RF weights, fold+butterfly reduce.
// h layout [buf][rank][batch][64]. SPLIT-HALF delivery: ranks 0-3 credit
// mbLo, ranks 4-7 credit mbHi (per buffer). Step: waitLo -> compute K[0,256)
// -> waitHi -> compute K[256,512) — low-half FFMA overlaps high-half flight.
// Rep lanes STS results directly into local hs[nxt][rank]; 7 remote 512B
// bulk copies (self delivered by STS; expect_tx reduced for own half).
// ---------------------------------------------------------------------------
__global__ __launch_bounds__(512, 1) __cluster_dims__(8, 1, 1)
void scan_kernel(const float* __restrict__ Whh)
{
    __shared__ __align__(16) float hs[2][8][2][64];  // [buf][rank][batch][row] 8KB
    __shared__ __align__(8) ull fullmb[2][2];        // [buf][half]

    const int tid = threadIdx.x;
    const int w = tid >> 5, l = tid & 31;

    unsigned rank;
    asm("mov.u32 %0, %%cluster_ctarank;" : "=r"(rank));
    const int b0 = (int)(blockIdx.x >> 3) * 2;
    const int i0 = (int)rank * 64;
    const int myhalf = (rank >= 4) ? 1 : 0;

    // Weights: rows i0+w*4+r, k = c*128 + l*4 + {0..3}, as f32x2 pairs.
    ull wp[4][4][2];
#pragma unroll
    for (int r = 0; r < 4; r++)
#pragma unroll
        for (int c = 0; c < 4; c++) {
            ulonglong2 u = *(const ulonglong2*)
                (&Whh[(size_t)(i0 + w * 4 + r) * HID + c * 128 + l * 4]);
            wp[r][c][0] = u.x; wp[r][c][1] = u.y;
        }

    uint32_t hbase  = (uint32_t)__cvta_generic_to_shared(&hs[0][0][0][0]);
    uint32_t mbbase = (uint32_t)__cvta_generic_to_shared(&fullmb[0][0]);
    // local mbarrier addrs: fullmb[buf][half] = mbbase + buf*16 + half*8
    // expect_tx per half: 4*512 remote minus 512 if it's MY half (self by STS)
    const uint32_t expLo = (myhalf == 0) ? 1536u : 2048u;
    const uint32_t expHi = (myhalf == 1) ? 1536u : 2048u;

    // warp0 lanes 0-7 (l != rank): peer l's hs slot for MY slice + peer l's
    // half-mbarrier (my half).
    uint32_t rdst = 0, rmb = 0;
    if (w == 0 && l < 8) {
        uint32_t myslice = hbase + (uint32_t)(rank * 512); // &hs[0][rank][0][0]
        asm("mapa.shared::cluster.u32 %0, %1, %2;" : "=r"(rdst) : "r"(myslice), "r"(l));
        asm("mapa.shared::cluster.u32 %0, %1, %2;" : "=r"(rmb)  : "r"(mbbase), "r"(l));
        rmb += (uint32_t)(myhalf * 8);
    }

    // rep lanes (l%4==0) own (batch brep, row w*4+rrep) after the fold-reduce
    const int brep = (l >> 2) & 1;
    const int rrep = ((l >> 3) & 1) * 2 + ((l >> 4) & 1);
    const bool isrep = ((l & 3) == 0);
    // self-STS address for rep lane: hs[nxt][rank][brep][w*4+rrep]
    float* selfp = &hs[0][rank][brep][w * 4 + rrep];

    // Init: h(0)=0; mbarriers count=1; pre-arm buf1 (targets of s=0 copies).
    for (int i = tid; i < 2 * HID; i += 512) ((float*)hs[0])[i] = 0.f;
    if (tid == 0) {
#pragma unroll
        for (int bfi = 0; bfi < 2; bfi++)
#pragma unroll
            for (int h = 0; h < 2; h++)
                asm volatile("mbarrier.init.shared.b64 [%0], %1;"
                             :: "r"(mbbase + (uint32_t)(bfi * 16 + h * 8)), "r"(1u) : "memory");
        asm volatile("mbarrier.arrive.expect_tx.shared::cta.b64 _, [%0], %1;"
                     :: "r"(mbbase + 16u), "r"(expLo) : "memory");
        asm volatile("mbarrier.arrive.expect_tx.shared::cta.b64 _, [%0], %1;"
                     :: "r"(mbbase + 24u), "r"(expHi) : "memory");
    }
    __syncthreads();
    asm volatile("barrier.cluster.arrive.aligned;" ::: "memory");
    asm volatile("barrier.cluster.wait.aligned;" ::: "memory");

    int pb0 = 0, pb1 = 0;   // parity per buffer (Lo/Hi flip together)

    // xproj prefetch ring, 2 deep, on rep lanes
    const float* xpp = &g_xproj[(size_t)(b0 + brep) * HID + i0 + w * 4 + rrep];
    float xpA = 0.f, xpB = 0.f;
    if (isrep) {
        xpA = __ldcg(xpp);
        xpB = __ldcg(xpp + BATCH * HID);
        xpp += 2 * (size_t)BATCH * HID;
    }

    // per-lane base offset into hs slab: h[b][kchunk c] = hb[c*256 + b*64]
    const int lbase = (l >> 4) * 128 + (l & 15) * 4;

    for (int s = 0; s < SEQ; s++) {
        const int cur = s & 1, nxt = cur ^ 1;
        const uint32_t mbLo = mbbase + (uint32_t)(cur * 16);
        const uint32_t mbHi = mbLo + 8u;
        const uint32_t P = (uint32_t)((cur == 0) ? pb0 : pb1);

        // prefetch xp[s+2] BEFORE the waits (hides DRAM latency)
        float xpC = 0.f;
        if (isrep && s + 2 < SEQ) { xpC = __ldcg(xpp); xpp += (size_t)BATCH * HID; }

        const float* hb = &hs[cur][0][0][0] + lbase;
        ull acc[2][4];   // [batch][row]
#pragma unroll
        for (int b = 0; b < 2; b++)
#pragma unroll
            for (int r = 0; r < 4; r++) acc[b][r] = 0ull;

        // ---- LOW half: wait ranks 0-3 delivered, compute K in [0,256) ----
        if (s > 0) {
            asm volatile(
                "{\n\t.reg .pred p;\n\t"
                "W%=:\n\t"
                "mbarrier.try_wait.parity.acquire.cta.shared::cta.b64 p, [%0], %1, 0x989680;\n\t"
                "@!p bra W%=;\n\t}"
                :: "r"(mbLo), "r"(P) : "memory");
        }
        if (tid == 0)
            asm volatile("mbarrier.arrive.expect_tx.shared::cta.b64 _, [%0], %1;"
                         :: "r"(mbLo), "r"(expLo) : "memory");
#pragma unroll
        for (int b = 0; b < 2; b++) {
#pragma unroll
            for (int c = 0; c < 2; c++) {
                ulonglong2 hc = *(const ulonglong2*)(hb + c * 256 + b * 64);
#pragma unroll
                for (int r = 0; r < 4; r++) {
                    ffma2(acc[b][r], wp[r][c][0], hc.x);
                    ffma2(acc[b][r], wp[r][c][1], hc.y);
                }
            }
        }

        // ---- HIGH half: wait ranks 4-7, compute K in [256,512) ----
        if (s > 0) {
            asm volatile(
                "{\n\t.reg .pred p;\n\t"
                "W%=:\n\t"
                "mbarrier.try_wait.parity.acquire.cta.shared::cta.b64 p, [%0], %1, 0x989680;\n\t"
                "@!p bra W%=;\n\t}"
                :: "r"(mbHi), "r"(P) : "memory");
            if (cur == 0) pb0 ^= 1; else pb1 ^= 1;
        }
        if (tid == 0)
            asm volatile("mbarrier.arrive.expect_tx.shared::cta.b64 _, [%0], %1;"
                         :: "r"(mbHi), "r"(expHi) : "memory");
#pragma unroll
        for (int b = 0; b < 2; b++) {
#pragma unroll
            for (int c = 2; c < 4; c++) {
                ulonglong2 hc = *(const ulonglong2*)(hb + c * 256 + b * 64);
#pragma unroll
                for (int r = 0; r < 4; r++) {
                    ffma2(acc[b][r], wp[r][c][0], hc.x);
                    ffma2(acc[b][r], wp[r][c][1], hc.y);
                }
            }
        }

        float v[8];
#pragma unroll
        for (int b = 0; b < 2; b++)
#pragma unroll
            for (int r = 0; r < 4; r++) {
                float2 u = unpk(acc[b][r]);
                v[b * 4 + r] = u.x + u.y;
            }

        // fold-reduce: 8 values -> 1 per lane (9 shfls total)
        {
            const unsigned FM = 0xffffffffu;
            int hi2 = (l >> 2) & 1;
#pragma unroll
            for (int i = 0; i < 4; i++) {
                float send = hi2 ? v[i] : v[i + 4];
                float recv = __shfl_xor_sync(FM, send, 4);
                v[i] = (hi2 ? v[i + 4] : v[i]) + recv;
            }
            int hi3 = (l >> 3) & 1;
#pragma unroll
            for (int i = 0; i < 2; i++) {
                float send = hi3 ? v[i] : v[i + 2];
                float recv = __shfl_xor_sync(FM, send, 8);
                v[i] = (hi3 ? v[i + 2] : v[i]) + recv;
            }
            int hi4 = (l >> 4) & 1;
            {
                float send = hi4 ? v[0] : v[1];
                float recv = __shfl_xor_sync(FM, send, 16);
                v[0] = (hi4 ? v[1] : v[0]) + recv;
            }
            v[0] += __shfl_xor_sync(FM, v[0], 1);
            v[0] += __shfl_xor_sync(FM, v[0], 2);
        }
        // rep lanes finish output; STS directly into local hs[nxt][rank]
        if (isrep)
            selfp[nxt * 1024] = ftanh(v[0] + xpA);   // 1024 floats = buf stride
        __syncthreads();

        // warp0 lanes 0-7 (skip self): one 512B bulk copy to peer l
        if (w == 0 && l < 8 && l != (int)rank) {
            asm volatile("fence.proxy.async.shared::cta;" ::: "memory");
            asm volatile(
                "cp.async.bulk.shared::cluster.shared::cta.mbarrier::complete_tx::bytes"
                " [%0], [%1], %2, [%3];"
                :: "r"(rdst + (uint32_t)(nxt * 4096)),
                   "r"(hbase + (uint32_t)(nxt * 4096 + rank * 512)),
                   "r"(512u),
                   "r"(rmb + (uint32_t)(nxt * 16))
                : "memory");
        }
        xpA = xpB; xpB = xpC;
    }

    // final: h(SEQ) lands in hs[0] (SEQ even) under buf0 Lo+Hi
    {
        const uint32_t P = (uint32_t)pb0;
        asm volatile(
            "{\n\t.reg .pred p;\n\t"
            "W%=:\n\t"
            "mbarrier.try_wait.parity.acquire.cta.shared::cta.b64 p, [%0], %1, 0x989680;\n\t"
            "@!p bra W%=;\n\t}"
            :: "r"(mbbase), "r"(P) : "memory");
        asm volatile(
            "{\n\t.reg .pred p;\n\t"
            "W%=:\n\t"
            "mbarrier.try_wait.parity.acquire.cta.shared::cta.b64 p, [%0], %1, 0x989680;\n\t"
            "@!p bra W%=;\n\t}"
            :: "r"(mbbase + 8u), "r"(P) : "memory");
    }
    for (int idx = tid; idx < 2 * HID; idx += 512) {
        int b = idx >> 9;
        int k = idx & 511;
        g_hfin[(b0 + b) * HID + k] = hs[0][k >> 6][b][k & 63];
    }
}

// ---------------------------------------------------------------------------
// Kernel 3: out = h_final @ W_fc^T + b_fc.
// ---------------------------------------------------------------------------
__global__ __launch_bounds__(256) void fc_kernel(
    const float* __restrict__ Wfc, const float* __restrict__ bfc,
    float* __restrict__ out)
{
    __shared__ float hsm[HID];
    const int b = blockIdx.x;
    const int o0 = blockIdx.y * 32;
    const int tid = threadIdx.x;
    for (int i = tid; i < HID; i += 256) hsm[i] = g_hfin[b * HID + i];
    __syncthreads();
    const int w = tid >> 5, l = tid & 31;
#pragma unroll
    for (int oi = 0; oi < 4; oi++) {
        int o = o0 + w * 4 + oi;
        const float* wr = Wfc + (size_t)o * HID;
        float sum = 0.f;
#pragma unroll
        for (int j2 = 0; j2 < HID / 32; j2++)
            sum = fmaf(hsm[j2 * 32 + l], wr[j2 * 32 + l], sum);
#pragma unroll
        for (int off = 16; off > 0; off >>= 1)
            sum += __shfl_down_sync(0xffffffffu, sum, off);
        if (l == 0) out[b * HID + o] = sum + bfc[o];
    }
}

// ---------------------------------------------------------------------------
extern "C" void kernel_launch(void* const* d_in, const int* in_sizes, int n_in,
                              void* d_out, int out_size)
{
    const float* x   = (const float*)d_in[0];
    const float* Wxh = (const float*)d_in[1];
    const float* bxh = (const float*)d_in[2];
    const float* Whh = (const float*)d_in[3];
    const float* bhh = (const float*)d_in[4];
    const float* bh  = (const float*)d_in[5];
    const float* Wfc = (const float*)d_in[6];
    const float* bfc = (const float*)d_in[7];
    float* out = (float*)d_out;

    xproj_gemm<<<dim3(HID / 128, (BATCH * SEQ) / 128), 256>>>(x, Wxh, bxh, bhh, bh);
    scan_kernel<<<128, 512>>>(Whh);
    fc_kernel<<<dim3(BATCH, 16), 256>>>(Wfc, bfc, out);
}